// round 17
// baseline (speedup 1.0000x reference)
#include <cuda_runtime.h>
#include <cstdint>

// Problem dims (fixed by the reference setup)
#define NB 4      // batch
#define NQ 16     // queries used (of 20)
#define NQP 20    // queries stored in btn_dec
#define NT 8      // t
#define NHW 256   // h*w
#define HWT 16    // hw positions per block
#define QT 8      // q positions per block (4 chunks of 2)
#define NG 8      // heads

__device__ __forceinline__ void ffma2(unsigned long long& d,
                                      unsigned long long a,
                                      unsigned long long b) {
    asm("fma.rn.f32x2 %0, %1, %2, %0;" : "+l"(d) : "l"(a), "l"(b));
}
__device__ __forceinline__ unsigned long long pack2(float lo, float hi) {
    unsigned long long r;
    asm("mov.b64 %0, {%1, %2};" : "=l"(r) : "f"(lo), "f"(hi));
    return r;
}
__device__ __forceinline__ void unpack2(unsigned long long v, float& lo, float& hi) {
    asm("mov.b64 {%0, %1}, %2;" : "=f"(lo), "=f"(hi) : "l"(v));
}
// 16B async copy gmem -> smem (bypasses registers)
__device__ __forceinline__ void cp16(uint32_t saddr, const void* gptr) {
    asm volatile("cp.async.cg.shared.global [%0], [%1], 16;"
                 :: "r"(saddr), "l"(gptr));
}
__device__ __forceinline__ void cp_commit() {
    asm volatile("cp.async.commit_group;");
}
__device__ __forceinline__ void cp_wait_all() {
    asm volatile("cp.async.wait_group 0;");
}

// Swizzled float4-index within a 512-float row (head g, chunk c4 0..15):
// (c4+g)&15 skew -> conflict-free g-parallel reads, 1-cyc dec broadcasts.
__device__ __forceinline__ int sw_idx(int g, int c4) {
    return g * 16 + ((c4 + g) & 15);
}

// ---------------------------------------------------------------------------
// Fused kernel = R16 champion (45.8us) with the exposed A section halved:
//   cp.async stage enc(32KB)+dec(16KB)        [store-idle]
//   A(q0,q1) -> sc[0]                         [store-idle, HALF of before]
//   3 sections: weave A(q_{2p+2},q_{2p+3}) (1 c4-step per 2 rows)
//               into B(q_{2p},q_{2p+1})'s 32 store rows     [stores flow]
//   final section: B(q6,q7) 32 rows plain                   [stores flow]
// Grid: 1024 blocks = (b:4)x(t:8)x(hwtile:16)x(qh:2), 128 thr, 50KB smem.
// ---------------------------------------------------------------------------
__global__ void __launch_bounds__(128, 4) heatmap_fused(
    const float* __restrict__ dec,   // (4, 20, 8, 512)
    const float* __restrict__ enc,   // (4, 8, 256, 512)
    const float* __restrict__ Wm,    // (8, 512)
    const float* __restrict__ bias,  // (512,)
    float* __restrict__ out)         // (4, 16, 8, 256, 512)
{
    extern __shared__ char smem_raw[];
    ulonglong2* enc_s = reinterpret_cast<ulonglong2*>(smem_raw);            // 32 KB
    ulonglong2* dec_s = reinterpret_cast<ulonglong2*>(smem_raw + 32768);    // 16 KB
    float* sc_buf[2] = {
        reinterpret_cast<float*>(smem_raw + 49152),                         // 1 KB
        reinterpret_cast<float*>(smem_raw + 50176) };                       // 1 KB

    const int tid = threadIdx.x;
    const int bid = blockIdx.x;
    const int qh  = bid & 1;             // q half-of-16: q0 = qh*8
    const int hwt = (bid >> 1) & 15;     // hw tile (16 positions)
    const int t   = (bid >> 5) & 7;
    const int b   = bid >> 8;

    const uint32_t enc_sb = (uint32_t)__cvta_generic_to_shared(enc_s);
    const uint32_t dec_sb = (uint32_t)__cvta_generic_to_shared(dec_s);

    // ---- cp.async stage enc tile: 16 hw rows x 128 float4, swizzled ----
    {
        const float* encg = enc + ((size_t)((b * NT + t) * NHW + hwt * HWT)) * 512;
#pragma unroll
        for (int k = 0; k < 16; k++) {
            int i = tid + k * 128;           // 0..2047
            int hwl = i >> 7;
            int j   = i & 127;
            cp16(enc_sb + (hwl * 128 + sw_idx(j >> 4, j & 15)) * 16,
                 encg + (size_t)i * 4);
        }
    }
    // ---- cp.async stage dec tile: 8 q rows x 128 float4, swizzled ----
    {
#pragma unroll
        for (int k = 0; k < 8; k++) {
            int i = tid + k * 128;           // 0..1023
            int q = i >> 7;                  // local q 0..7
            int j = i & 127;
            cp16(dec_sb + (q * 128 + sw_idx(j >> 4, j & 15)) * 16,
                 dec + ((size_t)((b * NQP + qh * QT + q) * NT + t)) * 512 + j * 4);
        }
    }
    cp_commit();

    // W/bias into registers while cp.async is in flight
    const int f4 = tid;
    const unsigned long long* W2 = reinterpret_cast<const unsigned long long*>(Wm);
    unsigned long long wreg[NG][2];
#pragma unroll
    for (int g = 0; g < NG; g++) {
        wreg[g][0] = W2[g * 256 + f4 * 2];
        wreg[g][1] = W2[g * 256 + f4 * 2 + 1];
    }
    const unsigned long long* B2 = reinterpret_cast<const unsigned long long*>(bias);
    const unsigned long long bb0 = B2[f4 * 2];
    const unsigned long long bb1 = B2[f4 * 2 + 1];

    cp_wait_all();
    __syncthreads();

    // Phase-A thread mapping (persistent)
    const int ga  = tid & 7;
    const int hwa = tid >> 3;               // 0..15
    const ulonglong2* erow = enc_s + hwa * 128;

    // ---- A(q0,q1) -> sc[0]  (the only exposed A work) ----
    {
        unsigned long long acc[2] = {0ull, 0ull};
#pragma unroll 4
        for (int c4 = 0; c4 < 16; c4++) {
            const int cc = sw_idx(ga, c4);
            ulonglong2 e = erow[cc];
#pragma unroll
            for (int q = 0; q < 2; q++) {
                ulonglong2 d = dec_s[q * 128 + cc];
                ffma2(acc[q], e.x, d.x);
                ffma2(acc[q], e.y, d.y);
            }
        }
#pragma unroll
        for (int q = 0; q < 2; q++) {
            float lo, hi;
            unpack2(acc[q], lo, hi);
            sc_buf[0][(q * HWT + hwa) * NG + ga] = lo + hi;
        }
    }
    __syncthreads();

    // out float4 base: (((b*16 + qh*8)*8+t)*256 + hwt*16)*128 + f4
    float4* out4 = reinterpret_cast<float4*>(out)
        + ((size_t)((b * NQ + qh * QT) * NT + t) * NHW + hwt * HWT) * 128 + f4;
    // local q stride (float4): 8*256*128 = 262144 ; hwl stride: 128

// r in [0,32): q_local = r>>4 (0/1), hwl = r&15 ; global q = qbase + q_local
#define B_ROW(scf, r, qbase)                                                       \
    {                                                                              \
        float4 sA = (scf)[(r) * 2 + 0];                                            \
        float4 sB = (scf)[(r) * 2 + 1];                                            \
        unsigned long long a0 = bb0, a1 = bb1;                                     \
        unsigned long long sp;                                                     \
        sp = pack2(sA.x, sA.x); ffma2(a0, sp, wreg[0][0]); ffma2(a1, sp, wreg[0][1]); \
        sp = pack2(sA.y, sA.y); ffma2(a0, sp, wreg[1][0]); ffma2(a1, sp, wreg[1][1]); \
        sp = pack2(sA.z, sA.z); ffma2(a0, sp, wreg[2][0]); ffma2(a1, sp, wreg[2][1]); \
        sp = pack2(sA.w, sA.w); ffma2(a0, sp, wreg[3][0]); ffma2(a1, sp, wreg[3][1]); \
        sp = pack2(sB.x, sB.x); ffma2(a0, sp, wreg[4][0]); ffma2(a1, sp, wreg[4][1]); \
        sp = pack2(sB.y, sB.y); ffma2(a0, sp, wreg[5][0]); ffma2(a1, sp, wreg[5][1]); \
        sp = pack2(sB.z, sB.z); ffma2(a0, sp, wreg[6][0]); ffma2(a1, sp, wreg[6][1]); \
        sp = pack2(sB.w, sB.w); ffma2(a0, sp, wreg[7][0]); ffma2(a1, sp, wreg[7][1]); \
        float4 res;                                                                \
        asm("mov.b64 {%0, %1}, %2;" : "=f"(res.x), "=f"(res.y) : "l"(a0));         \
        asm("mov.b64 {%0, %1}, %2;" : "=f"(res.z), "=f"(res.w) : "l"(a1));         \
        res.x = fmaxf(res.x, 0.f);                                                 \
        res.y = fmaxf(res.y, 0.f);                                                 \
        res.z = fmaxf(res.z, 0.f);                                                 \
        res.w = fmaxf(res.w, 0.f);                                                 \
        const int q_   = ((r) >> 4) + (qbase);                                     \
        const int hwl_ = (r) & 15;                                                 \
        __stcs(&out4[(size_t)q_ * 262144 + hwl_ * 128], res);                      \
    }

    // ---- 4 sections of 32 rows; sections 0..2 weave the next 2-q A chunk ----
#pragma unroll
    for (int p = 0; p < 4; p++) {
        const int cur = p & 1;
        const int nxt = cur ^ 1;
        const bool more = (p < 3);
        const float4* scf = reinterpret_cast<const float4*>(sc_buf[cur]);
        const int qbase = p * 2;
        const ulonglong2* drow = dec_s + (qbase + 2) * 128;  // next chunk's dec

        unsigned long long acc[2] = {0ull, 0ull};
#pragma unroll 2
        for (int s = 0; s < 16; s++) {
            if (more) {
                // one c4-step of A(next 2 q) — registers only
                const int cc = sw_idx(ga, s);
                ulonglong2 e = erow[cc];
                ulonglong2 d0 = drow[cc];
                ulonglong2 d1 = drow[128 + cc];
                ffma2(acc[0], e.x, d0.x);
                ffma2(acc[0], e.y, d0.y);
                ffma2(acc[1], e.x, d1.x);
                ffma2(acc[1], e.y, d1.y);
            }
            // two B rows — streaming stores
            B_ROW(scf, s * 2 + 0, qbase);
            B_ROW(scf, s * 2 + 1, qbase);
        }
        if (more) {
#pragma unroll
            for (int q = 0; q < 2; q++) {
                float lo, hi;
                unpack2(acc[q], lo, hi);
                sc_buf[nxt][(q * HWT + hwa) * NG + ga] = lo + hi;
            }
            __syncthreads();
        }
    }
#undef B_ROW
}

extern "C" void kernel_launch(void* const* d_in, const int* in_sizes, int n_in,
                              void* d_out, int out_size)
{
    const float* dec  = (const float*)d_in[0];  // (4,20,8,512)
    const float* enc  = (const float*)d_in[1];  // (4,8,16,16,512)
    const float* Wm   = (const float*)d_in[2];  // (8,512)
    const float* bias = (const float*)d_in[3];  // (512,)
    float* out = (float*)d_out;                 // (4,16,8,16,16,512)

    const int smem = 52 * 1024;
    cudaFuncSetAttribute(heatmap_fused,
                         cudaFuncAttributeMaxDynamicSharedMemorySize, smem);

    // 1024 blocks = (b:4)x(t:8)x(hwtile:16)x(qh:2)
    heatmap_fused<<<NB * NT * (NHW / HWT) * 2, 128, smem>>>(dec, enc, Wm, bias, out);
}